// round 14
// baseline (speedup 1.0000x reference)
#include <cuda_runtime.h>
#include <cfloat>
#include <cstdint>

#define Bn  8
#define Ls  3136      // 56*56
#define Cn  64
#define HID 32
#define KN  30
#define NV  (Bn*Ls)   // 25088 global vertices/edges
#define CAP 1536      // candidate capacity (sbuf holds 1568 u64)
#define SBATCH 2      // samples per dist/select batch (2*39.3MB = 78.7MB < L2)

// ---------------- device scratch (static globals; no allocations) ----------------
__device__ float    g_sq  [NV];
__device__ float    g_d2  [(size_t)SBATCH*Ls*Ls];   // 78.7 MB, reused per batch (L2-resident)
__device__ int      g_nbr [(size_t)NV*KN];
__device__ int      g_dvi [NV];
__device__ int      g_off [NV];
__device__ int      g_cnt [NV];
__device__ int      g_adj [(size_t)NV*KN];
__device__ float    g_h1  [(size_t)NV*HID];
__device__ float    g_y1  [(size_t)NV*HID];
__device__ float    g_h2  [(size_t)NV*Cn];
__device__ float    g_y2  [(size_t)NV*Cn];

#define BN_SCALE 0.99999500003749969f
#define FLIPU(u) ((u) ^ ((unsigned)(((int)(u)) >> 31) | 0x80000000u))

__device__ __forceinline__ float unflip_f(unsigned v) {
    unsigned m = ((int)v < 0) ? 0x80000000u : 0xffffffffu;
    return __uint_as_float(v ^ m);
}

// ---------------- kernel 1: row squared norms + zero counters ----------------
__global__ void sq_kernel(const float* __restrict__ x) {
    int tid = threadIdx.x;
    int gv = blockIdx.x * 8 + (tid >> 5);
    int lane = tid & 31;
    const float* p = x + (size_t)gv * Cn;
    float a = p[lane] * p[lane] + p[lane + 32] * p[lane + 32];
    #pragma unroll
    for (int off = 16; off; off >>= 1) a += __shfl_down_sync(0xffffffffu, a, off);
    if (lane == 0) g_sq[gv] = a;
    int t = blockIdx.x * 256 + tid;
    if (t < NV) { g_cnt[t] = 0; g_dvi[t] = 0; }
}

// ---------------- kernel 2: d2 batch = sq_i + sq_j - 2*(ft @ ft^T), symmetric tiles ----
__global__ void __launch_bounds__(64) dist_kernel(const float* __restrict__ x, int sb) {
    int ti = blockIdx.y, tj = blockIdx.x;
    if (ti > tj) return;
    int sl = blockIdx.z;             // local sample in batch
    int s = sb + sl;                 // global sample
    const float* A  = x + (size_t)s * Ls * Cn;
    float*       D  = g_d2 + (size_t)sl * Ls * Ls;
    const float* sq = g_sq + s * Ls;
    int i0 = ti << 6, j0 = tj << 6;

    __shared__ __align__(16) float Ast[64][68];
    __shared__ __align__(16) float Bst[64][68];
    int tid = threadIdx.x;   // 64 threads

    for (int f = tid; f < 1024; f += 64) {
        int m = f >> 4, kq = (f & 15) << 2;
        float4 av = *(const float4*)(A + (size_t)(i0 + m) * Cn + kq);
        Ast[kq + 0][m] = av.x; Ast[kq + 1][m] = av.y; Ast[kq + 2][m] = av.z; Ast[kq + 3][m] = av.w;
        float4 bv = *(const float4*)(A + (size_t)(j0 + m) * Cn + kq);
        Bst[kq + 0][m] = bv.x; Bst[kq + 1][m] = bv.y; Bst[kq + 2][m] = bv.z; Bst[kq + 3][m] = bv.w;
    }
    __syncthreads();

    int m0 = (tid >> 3) << 3;
    int n0 = (tid & 7) << 3;
    float acc[8][8];
    #pragma unroll
    for (int r = 0; r < 8; r++)
        #pragma unroll
        for (int c = 0; c < 8; c++) acc[r][c] = 0.f;

    #pragma unroll 8
    for (int k = 0; k < 64; k++) {
        float a[8], b[8];
        *(float4*)(a)     = *(const float4*)&Ast[k][m0];
        *(float4*)(a + 4) = *(const float4*)&Ast[k][m0 + 4];
        *(float4*)(b)     = *(const float4*)&Bst[k][n0];
        *(float4*)(b + 4) = *(const float4*)&Bst[k][n0 + 4];
        #pragma unroll
        for (int r = 0; r < 8; r++)
            #pragma unroll
            for (int c = 0; c < 8; c++) acc[r][c] = fmaf(a[r], b[c], acc[r][c]);
    }

    float sqj[8], sqi[8];
    #pragma unroll
    for (int c = 0; c < 8; c++) sqj[c] = sq[j0 + n0 + c];
    #pragma unroll
    for (int r = 0; r < 8; r++) sqi[r] = sq[i0 + m0 + r];
    #pragma unroll
    for (int r = 0; r < 8; r++)
        #pragma unroll
        for (int c = 0; c < 8; c++) acc[r][c] = sqi[r] + sqj[c] - 2.f * acc[r][c];

    #pragma unroll
    for (int r = 0; r < 8; r++) {
        float* drow = D + (size_t)(i0 + m0 + r) * Ls + j0 + n0;
        *(float4*)(drow)     = make_float4(acc[r][0], acc[r][1], acc[r][2], acc[r][3]);
        *(float4*)(drow + 4) = make_float4(acc[r][4], acc[r][5], acc[r][6], acc[r][7]);
    }
    if (ti != tj) {
        #pragma unroll
        for (int c = 0; c < 8; c++) {
            float* drow = D + (size_t)(j0 + n0 + c) * Ls + i0 + m0;
            *(float4*)(drow)     = make_float4(acc[0][c], acc[1][c], acc[2][c], acc[3][c]);
            *(float4*)(drow + 4) = make_float4(acc[4][c], acc[5][c], acc[6][c], acc[7][c]);
        }
    }
}

// ---------------- kernel 3: fused warp-threshold + float filter + exact top-30 -------
__global__ void __launch_bounds__(256) select_kernel(int sb) {
    int sl = blockIdx.y, i = blockIdx.x;
    int s = sb + sl;
    int sB = s * Ls;
    int gv = sB + i;
    const float* row = g_d2 + ((size_t)sl * Ls + i) * Ls;
    const float4* rowf4 = (const float4*)row;

    __shared__ __align__(16) unsigned sbuf[Ls];     // 12.5 KB (cand u64 overlay / fallback keys)
    __shared__ unsigned samp_sm[256];
    __shared__ unsigned sTu[2];                     // flipped thresholds: [0]=6th, [1]=12th sample
    __shared__ int scnt;
    unsigned long long* cand = (unsigned long long*)sbuf;

    int tid = threadIdx.x;   // 256
    if (tid == 0) scnt = 0;

    // load entire row into registers (raw floats), coalesced (L2-hot)
    float4 f0 = rowf4[tid];
    float4 f1 = rowf4[tid + 256];
    float4 f2 = rowf4[tid + 512];
    float4 f3 = make_float4(FLT_MAX, FLT_MAX, FLT_MAX, FLT_MAX);
    bool rem = (tid < 784 - 768);
    if (rem) f3 = rowf4[tid + 768];

    // one sample per thread (stride 12) -> smem as flipped key
    samp_sm[tid] = FLIPU(__float_as_uint(row[tid * 12]));
    __syncthreads();

    // warp 0: extract 12 smallest samples; record 6th and 12th
    if (tid < 32) {
        unsigned v[8];
        #pragma unroll
        for (int j = 0; j < 8; j++) v[j] = samp_sm[tid + 32 * j];
        #pragma unroll 1
        for (int r = 0; r < 12; r++) {
            unsigned long long m = ~0ull;
            #pragma unroll
            for (int j = 0; j < 8; j++) {
                unsigned long long p = ((unsigned long long)v[j] << 13) | (unsigned)(tid << 3) | (unsigned)j;
                m = (p < m) ? p : m;
            }
            #pragma unroll
            for (int o = 16; o; o >>= 1) {
                unsigned long long t2 = __shfl_down_sync(0xffffffffu, m, o);
                m = (t2 < m) ? t2 : m;
            }
            m = __shfl_sync(0xffffffffu, m, 0);
            if ((int)((m >> 3) & 31u) == tid) v[m & 7u] = 0xffffffffu;
            if (tid == 0 && r == 5)  sTu[0] = (unsigned)(m >> 13);
            if (tid == 0 && r == 11) sTu[1] = (unsigned)(m >> 13);
        }
    }
    __syncthreads();
    float Tf = unflip_f(sTu[0]);

    // float-domain filter: FLIPU applied only on hits (~74 expected)
    #define FPROC(ff, base) {                                                                  \
        if (ff.x <= Tf) { int p = atomicAdd(&scnt, 1); if (p < CAP) cand[p] = ((unsigned long long)FLIPU(__float_as_uint(ff.x)) << 32) | (unsigned)((base));     } \
        if (ff.y <= Tf) { int p = atomicAdd(&scnt, 1); if (p < CAP) cand[p] = ((unsigned long long)FLIPU(__float_as_uint(ff.y)) << 32) | (unsigned)((base) + 1); } \
        if (ff.z <= Tf) { int p = atomicAdd(&scnt, 1); if (p < CAP) cand[p] = ((unsigned long long)FLIPU(__float_as_uint(ff.z)) << 32) | (unsigned)((base) + 2); } \
        if (ff.w <= Tf) { int p = atomicAdd(&scnt, 1); if (p < CAP) cand[p] = ((unsigned long long)FLIPU(__float_as_uint(ff.w)) << 32) | (unsigned)((base) + 3); } \
    }
    FPROC(f0, tid * 4)
    FPROC(f1, (tid + 256) * 4)
    FPROC(f2, (tid + 512) * 4)
    if (rem) FPROC(f3, (tid + 768) * 4)
    __syncthreads();

    int cnt = scnt;
    if (cnt < KN) {
        // ~7% of rows: re-filter with looser 12th-sample threshold
        __syncthreads();
        if (tid == 0) scnt = 0;
        Tf = unflip_f(sTu[1]);
        __syncthreads();
        FPROC(f0, tid * 4)
        FPROC(f1, (tid + 256) * 4)
        FPROC(f2, (tid + 512) * 4)
        if (rem) FPROC(f3, (tid + 768) * 4)
        __syncthreads();
        cnt = scnt;
    }
    #undef FPROC

    int* nout = g_nbr + (size_t)gv * KN;
    int* dv = g_dvi + sB;

    if (cnt >= KN && cnt <= CAP) {
        for (int t = tid; t < cnt; t += 256) {
            unsigned long long K = cand[t];
            int r = 0;
            #pragma unroll 4
            for (int j = 0; j < cnt; j++) r += (cand[j] < K);
            if (r < KN) {
                int idx = (int)(K & 0xffffffffull);
                nout[r] = idx;
                atomicAdd(&dv[idx], 1);
            }
        }
    } else {
        // ultra-rare exact fallback: full-row rank select (flipped keys in smem)
        __syncthreads();
        #define STFL(ff, base) { \
            sbuf[(base)]     = FLIPU(__float_as_uint(ff.x)); \
            sbuf[(base) + 1] = FLIPU(__float_as_uint(ff.y)); \
            sbuf[(base) + 2] = FLIPU(__float_as_uint(ff.z)); \
            sbuf[(base) + 3] = FLIPU(__float_as_uint(ff.w)); \
        }
        STFL(f0, tid * 4)
        STFL(f1, (tid + 256) * 4)
        STFL(f2, (tid + 512) * 4)
        if (rem) STFL(f3, (tid + 768) * 4)
        #undef STFL
        __syncthreads();
        for (int t = tid; t < Ls; t += 256) {
            unsigned ut = sbuf[t];
            int r = 0;
            for (int j = 0; j < Ls; j++) {
                unsigned uj = sbuf[j];
                r += (uj < ut) || (uj == ut && j < t);
            }
            if (r < KN) {
                nout[r] = t;
                atomicAdd(&dv[t], 1);
            }
        }
    }
}

// ---------------- kernel 4: exclusive scan of degrees (shuffle-based) ----------------
__global__ void scan_kernel() {
    __shared__ int wsum[32];
    int tid = threadIdx.x;    // 1024
    int lane = tid & 31, w = tid >> 5;
    int start = tid * 25;
    int sum = 0;
    for (int t = start; t < start + 25 && t < NV; t++) sum += g_dvi[t];
    int v = sum;
    #pragma unroll
    for (int o = 1; o < 32; o <<= 1) {
        int n = __shfl_up_sync(0xffffffffu, v, o);
        if (lane >= o) v += n;
    }
    if (lane == 31) wsum[w] = v;
    __syncthreads();
    if (w == 0) {
        int sv = wsum[lane];
        #pragma unroll
        for (int o = 1; o < 32; o <<= 1) {
            int n = __shfl_up_sync(0xffffffffu, sv, o);
            if (lane >= o) sv += n;
        }
        wsum[lane] = sv;
    }
    __syncthreads();
    int excl = v - sum + ((w > 0) ? wsum[w - 1] : 0);
    for (int t = start; t < start + 25 && t < NV; t++) {
        g_off[t] = excl;
        excl += g_dvi[t];
    }
}

// ---------------- kernel 5: CSR fill (warp per edge) ----------------
__global__ void fill_kernel() {
    int s = blockIdx.y;
    int e = blockIdx.x * 8 + (threadIdx.x >> 5);
    int lane = threadIdx.x & 31;
    int ge = s * Ls + e;
    if (lane < KN) {
        int v  = g_nbr[(size_t)ge * KN + lane];
        int gv = s * Ls + v;
        int pos = atomicAdd(&g_cnt[gv], 1);
        g_adj[g_off[gv] + pos] = ge;
    }
}

// ---------------- kernel 6: theta1 + BN ----------------
__global__ void theta1_kernel(const float* __restrict__ x, const float* __restrict__ w1,
                              const float* __restrict__ b1, const float* __restrict__ g1,
                              const float* __restrict__ be1) {
    __shared__ float ws[Cn * HID];
    int tid = threadIdx.x;
    for (int t = tid; t < Cn * HID; t += 256) ws[t] = w1[t];
    __syncthreads();
    int gv = blockIdx.x * 8 + (tid >> 5);
    int lane = tid & 31;
    const float* f = x + (size_t)gv * Cn;
    float f0 = f[lane], f1 = f[lane + 32];
    float acc = 0.f;
    #pragma unroll
    for (int c = 0; c < 32; c++) acc = fmaf(__shfl_sync(0xffffffffu, f0, c), ws[c * HID + lane], acc);
    #pragma unroll
    for (int c = 0; c < 32; c++) acc = fmaf(__shfl_sync(0xffffffffu, f1, c), ws[(c + 32) * HID + lane], acc);
    g_h1[(size_t)gv * HID + lane] = (acc + b1[lane]) * (g1[lane] * BN_SCALE) + be1[lane];
}

// ---------------- kernel 7: v2e mean, conv1 ----------------
__global__ void v2e1_kernel() {
    int s = blockIdx.y;
    int e = blockIdx.x * 8 + (threadIdx.x >> 5);
    int lane = threadIdx.x & 31;
    int ge = s * Ls + e;
    const int* nb = g_nbr + (size_t)ge * KN;
    int myn = (lane < KN) ? nb[lane] : 0;
    const float* h = g_h1 + (size_t)s * Ls * HID;
    float acc = 0.f;
    #pragma unroll
    for (int j = 0; j < KN; j++) {
        int v = __shfl_sync(0xffffffffu, myn, j);
        acc += h[(size_t)v * HID + lane];
    }
    g_y1[(size_t)ge * HID + lane] = acc * (1.f / KN);
}

// ---------------- kernel 8: e2v mean + relu + theta2 + BN (fused) ----------------
__global__ void __launch_bounds__(256) e2v1t2_kernel(const float* __restrict__ w2,
                                                     const float* __restrict__ b2,
                                                     const float* __restrict__ g2,
                                                     const float* __restrict__ be2) {
    __shared__ float ws[HID * Cn];
    int tid = threadIdx.x;
    for (int t = tid; t < HID * Cn; t += 256) ws[t] = w2[t];
    __syncthreads();
    int gv = blockIdx.x * 8 + (tid >> 5);
    int lane = tid & 31;
    int cnt = g_dvi[gv];
    int off = g_off[gv];
    float acc = 0.f;
    for (int t = 0; t < cnt; t++) {
        int ge = g_adj[off + t];
        acc += g_y1[(size_t)ge * HID + lane];
    }
    float d = fmaxf((float)cnt, 1.f);
    float o = fmaxf(acc / d, 0.f);
    float a0 = 0.f, a1 = 0.f;
    #pragma unroll
    for (int c = 0; c < 32; c++) {
        float in = __shfl_sync(0xffffffffu, o, c);
        a0 = fmaf(in, ws[c * Cn + lane], a0);
        a1 = fmaf(in, ws[c * Cn + lane + 32], a1);
    }
    g_h2[(size_t)gv * Cn + lane]      = (a0 + b2[lane])      * (g2[lane]      * BN_SCALE) + be2[lane];
    g_h2[(size_t)gv * Cn + lane + 32] = (a1 + b2[lane + 32]) * (g2[lane + 32] * BN_SCALE) + be2[lane + 32];
}

// ---------------- kernel 9: v2e mean, conv2 ----------------
__global__ void v2e2_kernel() {
    int s = blockIdx.y;
    int e = blockIdx.x * 8 + (threadIdx.x >> 5);
    int lane = threadIdx.x & 31;
    int ge = s * Ls + e;
    const int* nb = g_nbr + (size_t)ge * KN;
    int myn = (lane < KN) ? nb[lane] : 0;
    const float* h = g_h2 + (size_t)s * Ls * Cn;
    float a0 = 0.f, a1 = 0.f;
    #pragma unroll
    for (int j = 0; j < KN; j++) {
        int v = __shfl_sync(0xffffffffu, myn, j);
        const float* hv = h + (size_t)v * Cn;
        a0 += hv[lane];
        a1 += hv[lane + 32];
    }
    g_y2[(size_t)ge * Cn + lane]      = a0 * (1.f / KN);
    g_y2[(size_t)ge * Cn + lane + 32] = a1 * (1.f / KN);
}

// ---------------- kernel 10: e2v mean, conv2 -> output ----------------
__global__ void e2v2_kernel(float* __restrict__ out) {
    int gv = blockIdx.x * 8 + (threadIdx.x >> 5);
    int lane = threadIdx.x & 31;
    int cnt = g_dvi[gv];
    int off = g_off[gv];
    float a0 = 0.f, a1 = 0.f;
    for (int t = 0; t < cnt; t++) {
        int ge = g_adj[off + t];
        const float* y = g_y2 + (size_t)ge * Cn;
        a0 += y[lane];
        a1 += y[lane + 32];
    }
    float d = fmaxf((float)cnt, 1.f);
    out[(size_t)gv * Cn + lane]      = a0 / d;
    out[(size_t)gv * Cn + lane + 32] = a1 / d;
}

// ---------------- launch ----------------
extern "C" void kernel_launch(void* const* d_in, const int* in_sizes, int n_in,
                              void* d_out, int out_size) {
    const float* x   = (const float*)d_in[0];
    const float* w1  = (const float*)d_in[1];
    const float* b1  = (const float*)d_in[2];
    const float* g1  = (const float*)d_in[3];
    const float* be1 = (const float*)d_in[4];
    const float* w2  = (const float*)d_in[5];
    const float* b2  = (const float*)d_in[6];
    const float* g2  = (const float*)d_in[7];
    const float* be2 = (const float*)d_in[8];
    float* out = (float*)d_out;

    sq_kernel<<<NV / 8, 256>>>(x);
    for (int sb = 0; sb < Bn; sb += SBATCH) {
        dist_kernel<<<dim3(Ls / 64, Ls / 64, SBATCH), 64>>>(x, sb);
        select_kernel<<<dim3(Ls, SBATCH), 256>>>(sb);
    }
    scan_kernel<<<1, 1024>>>();
    fill_kernel<<<dim3(Ls / 8, Bn), 256>>>();
    theta1_kernel<<<NV / 8, 256>>>(x, w1, b1, g1, be1);
    v2e1_kernel<<<dim3(Ls / 8, Bn), 256>>>();
    e2v1t2_kernel<<<NV / 8, 256>>>(w2, b2, g2, be2);
    v2e2_kernel<<<dim3(Ls / 8, Bn), 256>>>();
    e2v2_kernel<<<NV / 8, 256>>>(out);
}

// round 15
// speedup vs baseline: 1.0726x; 1.0726x over previous
#include <cuda_runtime.h>
#include <cfloat>
#include <cstdint>

#define Bn  8
#define Ls  3136      // 56*56
#define Cn  64
#define HID 32
#define KN  30
#define NV  (Bn*Ls)   // 25088 global vertices/edges
#define CAP 1536      // candidate capacity (sbuf holds 1568 u64)

// ---------------- device scratch (static globals; no allocations) ----------------
__device__ float    g_sq  [NV];
__device__ float    g_d2  [(size_t)Bn*Ls*Ls];   // 314.7 MB distance matrices
__device__ int      g_nbr [(size_t)NV*KN];
__device__ int      g_dvi [NV];
__device__ int      g_off [NV];
__device__ int      g_cnt [NV];
__device__ int      g_adj [(size_t)NV*KN];
__device__ float    g_h1  [(size_t)NV*HID];
__device__ float    g_y1  [(size_t)NV*HID];
__device__ float    g_h2  [(size_t)NV*Cn];
__device__ float    g_y2  [(size_t)NV*Cn];

#define BN_SCALE 0.99999500003749969f
#define FLIPU(u) ((u) ^ ((unsigned)(((int)(u)) >> 31) | 0x80000000u))

__device__ __forceinline__ float unflip_f(unsigned v) {
    unsigned m = ((int)v < 0) ? 0x80000000u : 0xffffffffu;
    return __uint_as_float(v ^ m);
}

// ---------------- kernel 1: row squared norms + zero counters ----------------
__global__ void sq_kernel(const float* __restrict__ x) {
    int tid = threadIdx.x;
    int gv = blockIdx.x * 8 + (tid >> 5);
    int lane = tid & 31;
    const float* p = x + (size_t)gv * Cn;
    float a = p[lane] * p[lane] + p[lane + 32] * p[lane + 32];
    #pragma unroll
    for (int off = 16; off; off >>= 1) a += __shfl_down_sync(0xffffffffu, a, off);
    if (lane == 0) g_sq[gv] = a;
    int t = blockIdx.x * 256 + tid;
    if (t < NV) { g_cnt[t] = 0; g_dvi[t] = 0; }
}

// ---------------- kernel 2: d2 = sq_i + sq_j - 2*(ft @ ft^T), symmetric tiles ----------------
__global__ void __launch_bounds__(64, 10) dist_kernel(const float* __restrict__ x) {
    int ti = blockIdx.y, tj = blockIdx.x;
    if (ti > tj) return;
    int s = blockIdx.z;
    const float* A  = x + (size_t)s * Ls * Cn;
    float*       D  = g_d2 + (size_t)s * Ls * Ls;
    const float* sq = g_sq + s * Ls;
    int i0 = ti << 6, j0 = tj << 6;

    __shared__ __align__(16) float Ast[64][68];
    __shared__ __align__(16) float Bst[64][68];
    int tid = threadIdx.x;   // 64 threads

    for (int f = tid; f < 1024; f += 64) {
        int m = f >> 4, kq = (f & 15) << 2;
        float4 av = *(const float4*)(A + (size_t)(i0 + m) * Cn + kq);
        Ast[kq + 0][m] = av.x; Ast[kq + 1][m] = av.y; Ast[kq + 2][m] = av.z; Ast[kq + 3][m] = av.w;
        float4 bv = *(const float4*)(A + (size_t)(j0 + m) * Cn + kq);
        Bst[kq + 0][m] = bv.x; Bst[kq + 1][m] = bv.y; Bst[kq + 2][m] = bv.z; Bst[kq + 3][m] = bv.w;
    }
    __syncthreads();

    int m0 = (tid >> 3) << 3;
    int n0 = (tid & 7) << 3;
    float acc[8][8];
    #pragma unroll
    for (int r = 0; r < 8; r++)
        #pragma unroll
        for (int c = 0; c < 8; c++) acc[r][c] = 0.f;

    #pragma unroll 8
    for (int k = 0; k < 64; k++) {
        float a[8], b[8];
        *(float4*)(a)     = *(const float4*)&Ast[k][m0];
        *(float4*)(a + 4) = *(const float4*)&Ast[k][m0 + 4];
        *(float4*)(b)     = *(const float4*)&Bst[k][n0];
        *(float4*)(b + 4) = *(const float4*)&Bst[k][n0 + 4];
        #pragma unroll
        for (int r = 0; r < 8; r++)
            #pragma unroll
            for (int c = 0; c < 8; c++) acc[r][c] = fmaf(a[r], b[c], acc[r][c]);
    }

    float sqj[8], sqi[8];
    #pragma unroll
    for (int c = 0; c < 8; c++) sqj[c] = sq[j0 + n0 + c];
    #pragma unroll
    for (int r = 0; r < 8; r++) sqi[r] = sq[i0 + m0 + r];
    #pragma unroll
    for (int r = 0; r < 8; r++)
        #pragma unroll
        for (int c = 0; c < 8; c++) acc[r][c] = sqi[r] + sqj[c] - 2.f * acc[r][c];

    #pragma unroll
    for (int r = 0; r < 8; r++) {
        float* drow = D + (size_t)(i0 + m0 + r) * Ls + j0 + n0;
        *(float4*)(drow)     = make_float4(acc[r][0], acc[r][1], acc[r][2], acc[r][3]);
        *(float4*)(drow + 4) = make_float4(acc[r][4], acc[r][5], acc[r][6], acc[r][7]);
    }
    if (ti != tj) {
        #pragma unroll
        for (int c = 0; c < 8; c++) {
            float* drow = D + (size_t)(j0 + n0 + c) * Ls + i0 + m0;
            *(float4*)(drow)     = make_float4(acc[0][c], acc[1][c], acc[2][c], acc[3][c]);
            *(float4*)(drow + 4) = make_float4(acc[4][c], acc[5][c], acc[6][c], acc[7][c]);
        }
    }
}

// ---------------- kernel 3: fused warp-threshold + float filter + exact top-30 -------
__global__ void __launch_bounds__(256) select_kernel() {
    int s = blockIdx.y, i = blockIdx.x;
    int sB = s * Ls;
    int gv = sB + i;
    const float* row = g_d2 + (size_t)gv * Ls;
    const float4* rowf4 = (const float4*)row;

    __shared__ __align__(16) unsigned sbuf[Ls];     // 12.5 KB (cand u64 overlay / fallback keys)
    __shared__ unsigned samp_sm[256];
    __shared__ unsigned sTu[2];                     // flipped thresholds: [0]=6th, [1]=12th sample
    __shared__ int scnt;
    unsigned long long* cand = (unsigned long long*)sbuf;

    int tid = threadIdx.x;   // 256
    if (tid == 0) scnt = 0;

    // load entire row into registers (raw floats), coalesced
    float4 f0 = rowf4[tid];
    float4 f1 = rowf4[tid + 256];
    float4 f2 = rowf4[tid + 512];
    float4 f3 = make_float4(FLT_MAX, FLT_MAX, FLT_MAX, FLT_MAX);
    bool rem = (tid < 784 - 768);
    if (rem) f3 = rowf4[tid + 768];

    // one sample per thread (stride 12, L1/L2-hot) -> smem as flipped key
    samp_sm[tid] = FLIPU(__float_as_uint(row[tid * 12]));
    __syncthreads();

    // warp 0: extract 12 smallest samples; record 6th and 12th
    if (tid < 32) {
        unsigned v[8];
        #pragma unroll
        for (int j = 0; j < 8; j++) v[j] = samp_sm[tid + 32 * j];
        #pragma unroll 1
        for (int r = 0; r < 12; r++) {
            unsigned long long m = ~0ull;
            #pragma unroll
            for (int j = 0; j < 8; j++) {
                unsigned long long p = ((unsigned long long)v[j] << 13) | (unsigned)(tid << 3) | (unsigned)j;
                m = (p < m) ? p : m;
            }
            #pragma unroll
            for (int o = 16; o; o >>= 1) {
                unsigned long long t2 = __shfl_down_sync(0xffffffffu, m, o);
                m = (t2 < m) ? t2 : m;
            }
            m = __shfl_sync(0xffffffffu, m, 0);
            if ((int)((m >> 3) & 31u) == tid) v[m & 7u] = 0xffffffffu;
            if (tid == 0 && r == 5)  sTu[0] = (unsigned)(m >> 13);
            if (tid == 0 && r == 11) sTu[1] = (unsigned)(m >> 13);
        }
    }
    __syncthreads();
    float Tf = unflip_f(sTu[0]);

    // float-domain filter: FLIPU applied only on hits (~74 expected)
    #define FPROC(ff, base) {                                                                  \
        if (ff.x <= Tf) { int p = atomicAdd(&scnt, 1); if (p < CAP) cand[p] = ((unsigned long long)FLIPU(__float_as_uint(ff.x)) << 32) | (unsigned)((base));     } \
        if (ff.y <= Tf) { int p = atomicAdd(&scnt, 1); if (p < CAP) cand[p] = ((unsigned long long)FLIPU(__float_as_uint(ff.y)) << 32) | (unsigned)((base) + 1); } \
        if (ff.z <= Tf) { int p = atomicAdd(&scnt, 1); if (p < CAP) cand[p] = ((unsigned long long)FLIPU(__float_as_uint(ff.z)) << 32) | (unsigned)((base) + 2); } \
        if (ff.w <= Tf) { int p = atomicAdd(&scnt, 1); if (p < CAP) cand[p] = ((unsigned long long)FLIPU(__float_as_uint(ff.w)) << 32) | (unsigned)((base) + 3); } \
    }
    FPROC(f0, tid * 4)
    FPROC(f1, (tid + 256) * 4)
    FPROC(f2, (tid + 512) * 4)
    if (rem) FPROC(f3, (tid + 768) * 4)
    __syncthreads();

    int cnt = scnt;
    if (cnt < KN) {
        // ~7% of rows: re-filter with looser 12th-sample threshold
        __syncthreads();
        if (tid == 0) scnt = 0;
        Tf = unflip_f(sTu[1]);
        __syncthreads();
        FPROC(f0, tid * 4)
        FPROC(f1, (tid + 256) * 4)
        FPROC(f2, (tid + 512) * 4)
        if (rem) FPROC(f3, (tid + 768) * 4)
        __syncthreads();
        cnt = scnt;
    }
    #undef FPROC

    int* nout = g_nbr + (size_t)gv * KN;
    int* dv = g_dvi + sB;

    if (cnt >= KN && cnt <= CAP) {
        for (int t = tid; t < cnt; t += 256) {
            unsigned long long K = cand[t];
            int r = 0;
            #pragma unroll 4
            for (int j = 0; j < cnt; j++) r += (cand[j] < K);
            if (r < KN) {
                int idx = (int)(K & 0xffffffffull);
                nout[r] = idx;
                atomicAdd(&dv[idx], 1);
            }
        }
    } else {
        // ultra-rare exact fallback: full-row rank select (flipped keys in smem)
        __syncthreads();
        #define STFL(ff, base) { \
            sbuf[(base)]     = FLIPU(__float_as_uint(ff.x)); \
            sbuf[(base) + 1] = FLIPU(__float_as_uint(ff.y)); \
            sbuf[(base) + 2] = FLIPU(__float_as_uint(ff.z)); \
            sbuf[(base) + 3] = FLIPU(__float_as_uint(ff.w)); \
        }
        STFL(f0, tid * 4)
        STFL(f1, (tid + 256) * 4)
        STFL(f2, (tid + 512) * 4)
        if (rem) STFL(f3, (tid + 768) * 4)
        #undef STFL
        __syncthreads();
        for (int t = tid; t < Ls; t += 256) {
            unsigned ut = sbuf[t];
            int r = 0;
            for (int j = 0; j < Ls; j++) {
                unsigned uj = sbuf[j];
                r += (uj < ut) || (uj == ut && j < t);
            }
            if (r < KN) {
                nout[r] = t;
                atomicAdd(&dv[t], 1);
            }
        }
    }
}

// ---------------- kernel 4: exclusive scan of degrees (shuffle-based) ----------------
__global__ void scan_kernel() {
    __shared__ int wsum[32];
    int tid = threadIdx.x;    // 1024
    int lane = tid & 31, w = tid >> 5;
    int start = tid * 25;
    int sum = 0;
    for (int t = start; t < start + 25 && t < NV; t++) sum += g_dvi[t];
    int v = sum;
    #pragma unroll
    for (int o = 1; o < 32; o <<= 1) {
        int n = __shfl_up_sync(0xffffffffu, v, o);
        if (lane >= o) v += n;
    }
    if (lane == 31) wsum[w] = v;
    __syncthreads();
    if (w == 0) {
        int sv = wsum[lane];
        #pragma unroll
        for (int o = 1; o < 32; o <<= 1) {
            int n = __shfl_up_sync(0xffffffffu, sv, o);
            if (lane >= o) sv += n;
        }
        wsum[lane] = sv;
    }
    __syncthreads();
    int excl = v - sum + ((w > 0) ? wsum[w - 1] : 0);
    for (int t = start; t < start + 25 && t < NV; t++) {
        g_off[t] = excl;
        excl += g_dvi[t];
    }
}

// ---------------- kernel 5: CSR fill (warp per edge) ----------------
__global__ void fill_kernel() {
    int s = blockIdx.y;
    int e = blockIdx.x * 8 + (threadIdx.x >> 5);
    int lane = threadIdx.x & 31;
    int ge = s * Ls + e;
    if (lane < KN) {
        int v  = g_nbr[(size_t)ge * KN + lane];
        int gv = s * Ls + v;
        int pos = atomicAdd(&g_cnt[gv], 1);
        g_adj[g_off[gv] + pos] = ge;
    }
}

// ---------------- kernel 6: theta1 + BN ----------------
__global__ void theta1_kernel(const float* __restrict__ x, const float* __restrict__ w1,
                              const float* __restrict__ b1, const float* __restrict__ g1,
                              const float* __restrict__ be1) {
    __shared__ float ws[Cn * HID];
    int tid = threadIdx.x;
    for (int t = tid; t < Cn * HID; t += 256) ws[t] = w1[t];
    __syncthreads();
    int gv = blockIdx.x * 8 + (tid >> 5);
    int lane = tid & 31;
    const float* f = x + (size_t)gv * Cn;
    float f0 = f[lane], f1 = f[lane + 32];
    float acc = 0.f;
    #pragma unroll
    for (int c = 0; c < 32; c++) acc = fmaf(__shfl_sync(0xffffffffu, f0, c), ws[c * HID + lane], acc);
    #pragma unroll
    for (int c = 0; c < 32; c++) acc = fmaf(__shfl_sync(0xffffffffu, f1, c), ws[(c + 32) * HID + lane], acc);
    g_h1[(size_t)gv * HID + lane] = (acc + b1[lane]) * (g1[lane] * BN_SCALE) + be1[lane];
}

// ---------------- kernel 7: v2e mean, conv1 ----------------
__global__ void v2e1_kernel() {
    int s = blockIdx.y;
    int e = blockIdx.x * 8 + (threadIdx.x >> 5);
    int lane = threadIdx.x & 31;
    int ge = s * Ls + e;
    const int* nb = g_nbr + (size_t)ge * KN;
    int myn = (lane < KN) ? nb[lane] : 0;
    const float* h = g_h1 + (size_t)s * Ls * HID;
    float acc = 0.f;
    #pragma unroll
    for (int j = 0; j < KN; j++) {
        int v = __shfl_sync(0xffffffffu, myn, j);
        acc += h[(size_t)v * HID + lane];
    }
    g_y1[(size_t)ge * HID + lane] = acc * (1.f / KN);
}

// ---------------- kernel 8: e2v mean + relu + theta2 + BN (fused) ----------------
__global__ void __launch_bounds__(256) e2v1t2_kernel(const float* __restrict__ w2,
                                                     const float* __restrict__ b2,
                                                     const float* __restrict__ g2,
                                                     const float* __restrict__ be2) {
    __shared__ float ws[HID * Cn];
    int tid = threadIdx.x;
    for (int t = tid; t < HID * Cn; t += 256) ws[t] = w2[t];
    __syncthreads();
    int gv = blockIdx.x * 8 + (tid >> 5);
    int lane = tid & 31;
    int cnt = g_dvi[gv];
    int off = g_off[gv];
    float acc = 0.f;
    for (int t = 0; t < cnt; t++) {
        int ge = g_adj[off + t];
        acc += g_y1[(size_t)ge * HID + lane];
    }
    float d = fmaxf((float)cnt, 1.f);
    float o = fmaxf(acc / d, 0.f);
    float a0 = 0.f, a1 = 0.f;
    #pragma unroll
    for (int c = 0; c < 32; c++) {
        float in = __shfl_sync(0xffffffffu, o, c);
        a0 = fmaf(in, ws[c * Cn + lane], a0);
        a1 = fmaf(in, ws[c * Cn + lane + 32], a1);
    }
    g_h2[(size_t)gv * Cn + lane]      = (a0 + b2[lane])      * (g2[lane]      * BN_SCALE) + be2[lane];
    g_h2[(size_t)gv * Cn + lane + 32] = (a1 + b2[lane + 32]) * (g2[lane + 32] * BN_SCALE) + be2[lane + 32];
}

// ---------------- kernel 9: v2e mean, conv2 ----------------
__global__ void v2e2_kernel() {
    int s = blockIdx.y;
    int e = blockIdx.x * 8 + (threadIdx.x >> 5);
    int lane = threadIdx.x & 31;
    int ge = s * Ls + e;
    const int* nb = g_nbr + (size_t)ge * KN;
    int myn = (lane < KN) ? nb[lane] : 0;
    const float* h = g_h2 + (size_t)s * Ls * Cn;
    float a0 = 0.f, a1 = 0.f;
    #pragma unroll
    for (int j = 0; j < KN; j++) {
        int v = __shfl_sync(0xffffffffu, myn, j);
        const float* hv = h + (size_t)v * Cn;
        a0 += hv[lane];
        a1 += hv[lane + 32];
    }
    g_y2[(size_t)ge * Cn + lane]      = a0 * (1.f / KN);
    g_y2[(size_t)ge * Cn + lane + 32] = a1 * (1.f / KN);
}

// ---------------- kernel 10: e2v mean, conv2 -> output ----------------
__global__ void e2v2_kernel(float* __restrict__ out) {
    int gv = blockIdx.x * 8 + (threadIdx.x >> 5);
    int lane = threadIdx.x & 31;
    int cnt = g_dvi[gv];
    int off = g_off[gv];
    float a0 = 0.f, a1 = 0.f;
    for (int t = 0; t < cnt; t++) {
        int ge = g_adj[off + t];
        const float* y = g_y2 + (size_t)ge * Cn;
        a0 += y[lane];
        a1 += y[lane + 32];
    }
    float d = fmaxf((float)cnt, 1.f);
    out[(size_t)gv * Cn + lane]      = a0 / d;
    out[(size_t)gv * Cn + lane + 32] = a1 / d;
}

// ---------------- launch ----------------
extern "C" void kernel_launch(void* const* d_in, const int* in_sizes, int n_in,
                              void* d_out, int out_size) {
    const float* x   = (const float*)d_in[0];
    const float* w1  = (const float*)d_in[1];
    const float* b1  = (const float*)d_in[2];
    const float* g1  = (const float*)d_in[3];
    const float* be1 = (const float*)d_in[4];
    const float* w2  = (const float*)d_in[5];
    const float* b2  = (const float*)d_in[6];
    const float* g2  = (const float*)d_in[7];
    const float* be2 = (const float*)d_in[8];
    float* out = (float*)d_out;

    sq_kernel<<<NV / 8, 256>>>(x);
    dist_kernel<<<dim3(Ls / 64, Ls / 64, Bn), 64>>>(x);
    select_kernel<<<dim3(Ls, Bn), 256>>>();
    scan_kernel<<<1, 1024>>>();
    fill_kernel<<<dim3(Ls / 8, Bn), 256>>>();
    theta1_kernel<<<NV / 8, 256>>>(x, w1, b1, g1, be1);
    v2e1_kernel<<<dim3(Ls / 8, Bn), 256>>>();
    e2v1t2_kernel<<<NV / 8, 256>>>(w2, b2, g2, be2);
    v2e2_kernel<<<dim3(Ls / 8, Bn), 256>>>();
    e2v2_kernel<<<NV / 8, 256>>>(out);
}

// round 16
// speedup vs baseline: 1.1144x; 1.0390x over previous
#include <cuda_runtime.h>
#include <cfloat>
#include <cstdint>

#define Bn  8
#define Ls  3136      // 56*56
#define Cn  64
#define HID 32
#define KN  30
#define NV  (Bn*Ls)   // 25088 global vertices/edges
#define CAP 1536      // candidate capacity (sbuf holds 1568 u64)

// ---------------- device scratch (static globals; no allocations) ----------------
__device__ float    g_sq  [NV];
__device__ float    g_d2  [(size_t)Bn*Ls*Ls];   // 314.7 MB distance matrices
__device__ int      g_nbr [(size_t)NV*KN];
__device__ int      g_dvi [NV];
__device__ int      g_off [NV];
__device__ int      g_cnt [NV];
__device__ int      g_adj [(size_t)NV*KN];
__device__ float    g_h1  [(size_t)NV*HID];
__device__ float    g_y1  [(size_t)NV*HID];
__device__ float    g_h2  [(size_t)NV*Cn];
__device__ float    g_y2  [(size_t)NV*Cn];

#define BN_SCALE 0.99999500003749969f
#define FLIPU(u) ((u) ^ ((unsigned)(((int)(u)) >> 31) | 0x80000000u))

__device__ __forceinline__ float unflip_f(unsigned v) {
    unsigned m = ((int)v < 0) ? 0x80000000u : 0xffffffffu;
    return __uint_as_float(v ^ m);
}

// ---------------- kernel 1: row squared norms + zero counters ----------------
__global__ void sq_kernel(const float* __restrict__ x) {
    int tid = threadIdx.x;
    int gv = blockIdx.x * 8 + (tid >> 5);
    int lane = tid & 31;
    const float* p = x + (size_t)gv * Cn;
    float a = p[lane] * p[lane] + p[lane + 32] * p[lane + 32];
    #pragma unroll
    for (int off = 16; off; off >>= 1) a += __shfl_down_sync(0xffffffffu, a, off);
    if (lane == 0) g_sq[gv] = a;
    int t = blockIdx.x * 256 + tid;
    if (t < NV) { g_cnt[t] = 0; g_dvi[t] = 0; }
}

// ---------------- kernel 2: d2 = sq_i + sq_j - 2*(ft @ ft^T) ----------------
// 64x64 tile, 128 threads (8x4 micro-tile): same smem (34.8KB), 2x warps/SM vs 64-thread version.
__global__ void __launch_bounds__(128) dist_kernel(const float* __restrict__ x) {
    int ti = blockIdx.y, tj = blockIdx.x;
    if (ti > tj) return;
    int s = blockIdx.z;
    const float* A  = x + (size_t)s * Ls * Cn;
    float*       D  = g_d2 + (size_t)s * Ls * Ls;
    const float* sq = g_sq + s * Ls;
    int i0 = ti << 6, j0 = tj << 6;

    __shared__ __align__(16) float Ast[64][68];
    __shared__ __align__(16) float Bst[64][68];
    int tid = threadIdx.x;   // 128 threads

    for (int f = tid; f < 1024; f += 128) {
        int m = f >> 4, kq = (f & 15) << 2;
        float4 av = *(const float4*)(A + (size_t)(i0 + m) * Cn + kq);
        Ast[kq + 0][m] = av.x; Ast[kq + 1][m] = av.y; Ast[kq + 2][m] = av.z; Ast[kq + 3][m] = av.w;
        float4 bv = *(const float4*)(A + (size_t)(j0 + m) * Cn + kq);
        Bst[kq + 0][m] = bv.x; Bst[kq + 1][m] = bv.y; Bst[kq + 2][m] = bv.z; Bst[kq + 3][m] = bv.w;
    }
    __syncthreads();

    int m0 = (tid >> 4) << 3;   // 8 row-groups of 8
    int n0 = (tid & 15) << 2;   // 16 col-groups of 4
    float acc[8][4];
    #pragma unroll
    for (int r = 0; r < 8; r++)
        #pragma unroll
        for (int c = 0; c < 4; c++) acc[r][c] = 0.f;

    #pragma unroll 8
    for (int k = 0; k < 64; k++) {
        float a[8], b[4];
        *(float4*)(a)     = *(const float4*)&Ast[k][m0];
        *(float4*)(a + 4) = *(const float4*)&Ast[k][m0 + 4];
        *(float4*)(b)     = *(const float4*)&Bst[k][n0];
        #pragma unroll
        for (int r = 0; r < 8; r++)
            #pragma unroll
            for (int c = 0; c < 4; c++) acc[r][c] = fmaf(a[r], b[c], acc[r][c]);
    }

    float sqj[4], sqi[8];
    #pragma unroll
    for (int c = 0; c < 4; c++) sqj[c] = sq[j0 + n0 + c];
    #pragma unroll
    for (int r = 0; r < 8; r++) sqi[r] = sq[i0 + m0 + r];
    #pragma unroll
    for (int r = 0; r < 8; r++)
        #pragma unroll
        for (int c = 0; c < 4; c++) acc[r][c] = sqi[r] + sqj[c] - 2.f * acc[r][c];

    #pragma unroll
    for (int r = 0; r < 8; r++) {
        float* drow = D + (size_t)(i0 + m0 + r) * Ls + j0 + n0;
        *(float4*)(drow) = make_float4(acc[r][0], acc[r][1], acc[r][2], acc[r][3]);
    }
    if (ti != tj) {
        #pragma unroll
        for (int c = 0; c < 4; c++) {
            float* drow = D + (size_t)(j0 + n0 + c) * Ls + i0 + m0;
            *(float4*)(drow)     = make_float4(acc[0][c], acc[1][c], acc[2][c], acc[3][c]);
            *(float4*)(drow + 4) = make_float4(acc[4][c], acc[5][c], acc[6][c], acc[7][c]);
        }
    }
}

// ---------------- kernel 3: fused warp-threshold + float filter + exact top-30 -------
__global__ void __launch_bounds__(256) select_kernel() {
    int s = blockIdx.y, i = blockIdx.x;
    int sB = s * Ls;
    int gv = sB + i;
    const float* row = g_d2 + (size_t)gv * Ls;
    const float4* rowf4 = (const float4*)row;

    __shared__ __align__(16) unsigned sbuf[Ls];     // 12.5 KB (cand u64 overlay / fallback keys)
    __shared__ unsigned samp_sm[256];
    __shared__ unsigned sTu[2];                     // flipped thresholds: [0]=6th, [1]=12th sample
    __shared__ int scnt;
    unsigned long long* cand = (unsigned long long*)sbuf;

    int tid = threadIdx.x;   // 256
    if (tid == 0) scnt = 0;

    // load entire row into registers (raw floats), coalesced
    float4 f0 = rowf4[tid];
    float4 f1 = rowf4[tid + 256];
    float4 f2 = rowf4[tid + 512];
    float4 f3 = make_float4(FLT_MAX, FLT_MAX, FLT_MAX, FLT_MAX);
    bool rem = (tid < 784 - 768);
    if (rem) f3 = rowf4[tid + 768];

    // one sample per thread (stride 12, L1/L2-hot) -> smem as flipped key
    samp_sm[tid] = FLIPU(__float_as_uint(row[tid * 12]));
    __syncthreads();

    // warp 0: extract 12 smallest samples; record 6th and 12th
    if (tid < 32) {
        unsigned v[8];
        #pragma unroll
        for (int j = 0; j < 8; j++) v[j] = samp_sm[tid + 32 * j];
        #pragma unroll 1
        for (int r = 0; r < 12; r++) {
            unsigned long long m = ~0ull;
            #pragma unroll
            for (int j = 0; j < 8; j++) {
                unsigned long long p = ((unsigned long long)v[j] << 13) | (unsigned)(tid << 3) | (unsigned)j;
                m = (p < m) ? p : m;
            }
            #pragma unroll
            for (int o = 16; o; o >>= 1) {
                unsigned long long t2 = __shfl_down_sync(0xffffffffu, m, o);
                m = (t2 < m) ? t2 : m;
            }
            m = __shfl_sync(0xffffffffu, m, 0);
            if ((int)((m >> 3) & 31u) == tid) v[m & 7u] = 0xffffffffu;
            if (tid == 0 && r == 5)  sTu[0] = (unsigned)(m >> 13);
            if (tid == 0 && r == 11) sTu[1] = (unsigned)(m >> 13);
        }
    }
    __syncthreads();
    float Tf = unflip_f(sTu[0]);

    // float-domain filter: FLIPU applied only on hits (~74 expected)
    #define FPROC(ff, base) {                                                                  \
        if (ff.x <= Tf) { int p = atomicAdd(&scnt, 1); if (p < CAP) cand[p] = ((unsigned long long)FLIPU(__float_as_uint(ff.x)) << 32) | (unsigned)((base));     } \
        if (ff.y <= Tf) { int p = atomicAdd(&scnt, 1); if (p < CAP) cand[p] = ((unsigned long long)FLIPU(__float_as_uint(ff.y)) << 32) | (unsigned)((base) + 1); } \
        if (ff.z <= Tf) { int p = atomicAdd(&scnt, 1); if (p < CAP) cand[p] = ((unsigned long long)FLIPU(__float_as_uint(ff.z)) << 32) | (unsigned)((base) + 2); } \
        if (ff.w <= Tf) { int p = atomicAdd(&scnt, 1); if (p < CAP) cand[p] = ((unsigned long long)FLIPU(__float_as_uint(ff.w)) << 32) | (unsigned)((base) + 3); } \
    }
    FPROC(f0, tid * 4)
    FPROC(f1, (tid + 256) * 4)
    FPROC(f2, (tid + 512) * 4)
    if (rem) FPROC(f3, (tid + 768) * 4)
    __syncthreads();

    int cnt = scnt;
    if (cnt < KN) {
        // ~7% of rows: re-filter with looser 12th-sample threshold
        __syncthreads();
        if (tid == 0) scnt = 0;
        Tf = unflip_f(sTu[1]);
        __syncthreads();
        FPROC(f0, tid * 4)
        FPROC(f1, (tid + 256) * 4)
        FPROC(f2, (tid + 512) * 4)
        if (rem) FPROC(f3, (tid + 768) * 4)
        __syncthreads();
        cnt = scnt;
    }
    #undef FPROC

    int* nout = g_nbr + (size_t)gv * KN;
    int* dv = g_dvi + sB;

    if (cnt >= KN && cnt <= CAP) {
        for (int t = tid; t < cnt; t += 256) {
            unsigned long long K = cand[t];
            int r = 0;
            #pragma unroll 4
            for (int j = 0; j < cnt; j++) r += (cand[j] < K);
            if (r < KN) {
                int idx = (int)(K & 0xffffffffull);
                nout[r] = idx;
                atomicAdd(&dv[idx], 1);
            }
        }
    } else {
        // ultra-rare exact fallback: full-row rank select (flipped keys in smem)
        __syncthreads();
        #define STFL(ff, base) { \
            sbuf[(base)]     = FLIPU(__float_as_uint(ff.x)); \
            sbuf[(base) + 1] = FLIPU(__float_as_uint(ff.y)); \
            sbuf[(base) + 2] = FLIPU(__float_as_uint(ff.z)); \
            sbuf[(base) + 3] = FLIPU(__float_as_uint(ff.w)); \
        }
        STFL(f0, tid * 4)
        STFL(f1, (tid + 256) * 4)
        STFL(f2, (tid + 512) * 4)
        if (rem) STFL(f3, (tid + 768) * 4)
        #undef STFL
        __syncthreads();
        for (int t = tid; t < Ls; t += 256) {
            unsigned ut = sbuf[t];
            int r = 0;
            for (int j = 0; j < Ls; j++) {
                unsigned uj = sbuf[j];
                r += (uj < ut) || (uj == ut && j < t);
            }
            if (r < KN) {
                nout[r] = t;
                atomicAdd(&dv[t], 1);
            }
        }
    }
}

// ---------------- kernel 4: exclusive scan of degrees (shuffle-based) ----------------
__global__ void scan_kernel() {
    __shared__ int wsum[32];
    int tid = threadIdx.x;    // 1024
    int lane = tid & 31, w = tid >> 5;
    int start = tid * 25;
    int sum = 0;
    for (int t = start; t < start + 25 && t < NV; t++) sum += g_dvi[t];
    int v = sum;
    #pragma unroll
    for (int o = 1; o < 32; o <<= 1) {
        int n = __shfl_up_sync(0xffffffffu, v, o);
        if (lane >= o) v += n;
    }
    if (lane == 31) wsum[w] = v;
    __syncthreads();
    if (w == 0) {
        int sv = wsum[lane];
        #pragma unroll
        for (int o = 1; o < 32; o <<= 1) {
            int n = __shfl_up_sync(0xffffffffu, sv, o);
            if (lane >= o) sv += n;
        }
        wsum[lane] = sv;
    }
    __syncthreads();
    int excl = v - sum + ((w > 0) ? wsum[w - 1] : 0);
    for (int t = start; t < start + 25 && t < NV; t++) {
        g_off[t] = excl;
        excl += g_dvi[t];
    }
}

// ---------------- kernel 5: CSR fill (warp per edge) ----------------
__global__ void fill_kernel() {
    int s = blockIdx.y;
    int e = blockIdx.x * 8 + (threadIdx.x >> 5);
    int lane = threadIdx.x & 31;
    int ge = s * Ls + e;
    if (lane < KN) {
        int v  = g_nbr[(size_t)ge * KN + lane];
        int gv = s * Ls + v;
        int pos = atomicAdd(&g_cnt[gv], 1);
        g_adj[g_off[gv] + pos] = ge;
    }
}

// ---------------- kernel 6: theta1 + BN ----------------
__global__ void theta1_kernel(const float* __restrict__ x, const float* __restrict__ w1,
                              const float* __restrict__ b1, const float* __restrict__ g1,
                              const float* __restrict__ be1) {
    __shared__ float ws[Cn * HID];
    int tid = threadIdx.x;
    for (int t = tid; t < Cn * HID; t += 256) ws[t] = w1[t];
    __syncthreads();
    int gv = blockIdx.x * 8 + (tid >> 5);
    int lane = tid & 31;
    const float* f = x + (size_t)gv * Cn;
    float f0 = f[lane], f1 = f[lane + 32];
    float acc = 0.f;
    #pragma unroll
    for (int c = 0; c < 32; c++) acc = fmaf(__shfl_sync(0xffffffffu, f0, c), ws[c * HID + lane], acc);
    #pragma unroll
    for (int c = 0; c < 32; c++) acc = fmaf(__shfl_sync(0xffffffffu, f1, c), ws[(c + 32) * HID + lane], acc);
    g_h1[(size_t)gv * HID + lane] = (acc + b1[lane]) * (g1[lane] * BN_SCALE) + be1[lane];
}

// ---------------- kernel 7: v2e mean, conv1 ----------------
__global__ void v2e1_kernel() {
    int s = blockIdx.y;
    int e = blockIdx.x * 8 + (threadIdx.x >> 5);
    int lane = threadIdx.x & 31;
    int ge = s * Ls + e;
    const int* nb = g_nbr + (size_t)ge * KN;
    int myn = (lane < KN) ? nb[lane] : 0;
    const float* h = g_h1 + (size_t)s * Ls * HID;
    float acc = 0.f;
    #pragma unroll
    for (int j = 0; j < KN; j++) {
        int v = __shfl_sync(0xffffffffu, myn, j);
        acc += h[(size_t)v * HID + lane];
    }
    g_y1[(size_t)ge * HID + lane] = acc * (1.f / KN);
}

// ---------------- kernel 8: e2v mean + relu + theta2 + BN (fused) ----------------
__global__ void __launch_bounds__(256) e2v1t2_kernel(const float* __restrict__ w2,
                                                     const float* __restrict__ b2,
                                                     const float* __restrict__ g2,
                                                     const float* __restrict__ be2) {
    __shared__ float ws[HID * Cn];
    int tid = threadIdx.x;
    for (int t = tid; t < HID * Cn; t += 256) ws[t] = w2[t];
    __syncthreads();
    int gv = blockIdx.x * 8 + (tid >> 5);
    int lane = tid & 31;
    int cnt = g_dvi[gv];
    int off = g_off[gv];
    float acc = 0.f;
    for (int t = 0; t < cnt; t++) {
        int ge = g_adj[off + t];
        acc += g_y1[(size_t)ge * HID + lane];
    }
    float d = fmaxf((float)cnt, 1.f);
    float o = fmaxf(acc / d, 0.f);
    float a0 = 0.f, a1 = 0.f;
    #pragma unroll
    for (int c = 0; c < 32; c++) {
        float in = __shfl_sync(0xffffffffu, o, c);
        a0 = fmaf(in, ws[c * Cn + lane], a0);
        a1 = fmaf(in, ws[c * Cn + lane + 32], a1);
    }
    g_h2[(size_t)gv * Cn + lane]      = (a0 + b2[lane])      * (g2[lane]      * BN_SCALE) + be2[lane];
    g_h2[(size_t)gv * Cn + lane + 32] = (a1 + b2[lane + 32]) * (g2[lane + 32] * BN_SCALE) + be2[lane + 32];
}

// ---------------- kernel 9: v2e mean, conv2 ----------------
__global__ void v2e2_kernel() {
    int s = blockIdx.y;
    int e = blockIdx.x * 8 + (threadIdx.x >> 5);
    int lane = threadIdx.x & 31;
    int ge = s * Ls + e;
    const int* nb = g_nbr + (size_t)ge * KN;
    int myn = (lane < KN) ? nb[lane] : 0;
    const float* h = g_h2 + (size_t)s * Ls * Cn;
    float a0 = 0.f, a1 = 0.f;
    #pragma unroll
    for (int j = 0; j < KN; j++) {
        int v = __shfl_sync(0xffffffffu, myn, j);
        const float* hv = h + (size_t)v * Cn;
        a0 += hv[lane];
        a1 += hv[lane + 32];
    }
    g_y2[(size_t)ge * Cn + lane]      = a0 * (1.f / KN);
    g_y2[(size_t)ge * Cn + lane + 32] = a1 * (1.f / KN);
}

// ---------------- kernel 10: e2v mean, conv2 -> output ----------------
__global__ void e2v2_kernel(float* __restrict__ out) {
    int gv = blockIdx.x * 8 + (threadIdx.x >> 5);
    int lane = threadIdx.x & 31;
    int cnt = g_dvi[gv];
    int off = g_off[gv];
    float a0 = 0.f, a1 = 0.f;
    for (int t = 0; t < cnt; t++) {
        int ge = g_adj[off + t];
        const float* y = g_y2 + (size_t)ge * Cn;
        a0 += y[lane];
        a1 += y[lane + 32];
    }
    float d = fmaxf((float)cnt, 1.f);
    out[(size_t)gv * Cn + lane]      = a0 / d;
    out[(size_t)gv * Cn + lane + 32] = a1 / d;
}

// ---------------- launch ----------------
extern "C" void kernel_launch(void* const* d_in, const int* in_sizes, int n_in,
                              void* d_out, int out_size) {
    const float* x   = (const float*)d_in[0];
    const float* w1  = (const float*)d_in[1];
    const float* b1  = (const float*)d_in[2];
    const float* g1  = (const float*)d_in[3];
    const float* be1 = (const float*)d_in[4];
    const float* w2  = (const float*)d_in[5];
    const float* b2  = (const float*)d_in[6];
    const float* g2  = (const float*)d_in[7];
    const float* be2 = (const float*)d_in[8];
    float* out = (float*)d_out;

    sq_kernel<<<NV / 8, 256>>>(x);
    dist_kernel<<<dim3(Ls / 64, Ls / 64, Bn), 128>>>(x);
    select_kernel<<<dim3(Ls, Bn), 256>>>();
    scan_kernel<<<1, 1024>>>();
    fill_kernel<<<dim3(Ls / 8, Bn), 256>>>();
    theta1_kernel<<<NV / 8, 256>>>(x, w1, b1, g1, be1);
    v2e1_kernel<<<dim3(Ls / 8, Bn), 256>>>();
    e2v1t2_kernel<<<NV / 8, 256>>>(w2, b2, g2, be2);
    v2e2_kernel<<<dim3(Ls / 8, Bn), 256>>>();
    e2v2_kernel<<<NV / 8, 256>>>(out);
}